// round 3
// baseline (speedup 1.0000x reference)
#include <cuda_runtime.h>
#include <cuda_bf16.h>
#include <cstdint>

#define T_TOK 8192
#define D_DIM 1024
#define F_DIM 3584
#define N_EXP 8
#define N_ASSIGN (T_TOK * 2)            // 16384 expert assignments
#define BM 128
#define BK 32
#define MAX_TILES (N_ASSIGN / BM + N_EXP)  // 136

// ---------------- scratch (static __device__, allocation-free) ----------------
__device__ float g_h[(size_t)N_ASSIGN * F_DIM];   // intermediate SwiGLU output (fp32)
__device__ int   g_rowtok[N_ASSIGN];
__device__ float g_roww[N_ASSIGN];
__device__ int   g_route_e[N_ASSIGN];
__device__ float g_route_w[N_ASSIGN];
__device__ int   g_cnt[N_EXP];
__device__ int   g_cur[N_EXP];
__device__ int   g_off[N_EXP + 1];
__device__ int   g_tile_e[MAX_TILES];
__device__ int   g_tile_r0[MAX_TILES];
__device__ int   g_tile_rend[MAX_TILES];
__device__ int   g_ntiles;

// ---------------- helpers ----------------
__device__ __forceinline__ float f2tf(float f) {
    // round-to-nearest tf32 (unbiased) — REQUIRED: raw truncation biases result ~1e-3
    uint32_t r;
    asm("cvt.rna.tf32.f32 %0, %1;" : "=r"(r) : "f"(f));
    return __uint_as_float(r);
}

__device__ __forceinline__ void mma_tf32(float c[4], uint32_t a0, uint32_t a1,
                                         uint32_t a2, uint32_t a3,
                                         uint32_t b0, uint32_t b1) {
    asm volatile(
        "mma.sync.aligned.m16n8k8.row.col.f32.tf32.tf32.f32 "
        "{%0,%1,%2,%3}, {%4,%5,%6,%7}, {%8,%9}, {%0,%1,%2,%3};\n"
        : "+f"(c[0]), "+f"(c[1]), "+f"(c[2]), "+f"(c[3])
        : "r"(a0), "r"(a1), "r"(a2), "r"(a3), "r"(b0), "r"(b1));
}

// ---------------- small kernels ----------------
__global__ void k_reset() {
    int i = threadIdx.x;
    if (i < N_EXP) { g_cnt[i] = 0; g_cur[i] = 0; }
}

__global__ void k_zero(float4* p, int n4) {
    int stride = gridDim.x * blockDim.x;
    for (int i = blockIdx.x * blockDim.x + threadIdx.x; i < n4; i += stride)
        p[i] = make_float4(0.f, 0.f, 0.f, 0.f);
}

__global__ void k_router(const float* __restrict__ x, const float* __restrict__ gw,
                         float* __restrict__ logits_out) {
    int t = blockIdx.x;
    int tid = threadIdx.x;                 // 256 threads
    const float* xr = x + (size_t)t * D_DIM;

    float acc[N_EXP];
#pragma unroll
    for (int e = 0; e < N_EXP; e++) acc[e] = 0.f;

    for (int j = tid; j < D_DIM; j += 256) {
        float xv = xr[j];
#pragma unroll
        for (int e = 0; e < N_EXP; e++) acc[e] += xv * gw[e * D_DIM + j];
    }
#pragma unroll
    for (int e = 0; e < N_EXP; e++)
#pragma unroll
        for (int o = 16; o > 0; o >>= 1)
            acc[e] += __shfl_xor_sync(0xffffffffu, acc[e], o);

    __shared__ float wsum[8][N_EXP];
    __shared__ float sl[N_EXP];
    int wid = tid >> 5, lane = tid & 31;
    if (lane == 0) {
#pragma unroll
        for (int e = 0; e < N_EXP; e++) wsum[wid][e] = acc[e];
    }
    __syncthreads();
    if (tid < N_EXP) {
        float s = 0.f;
#pragma unroll
        for (int w = 0; w < 8; w++) s += wsum[w][tid];
        sl[tid] = s;
        logits_out[(size_t)t * N_EXP + tid] = s;   // raw router logits output
    }
    __syncthreads();
    if (tid == 0) {
        float l[N_EXP];
#pragma unroll
        for (int e = 0; e < N_EXP; e++) l[e] = sl[e];
        int i0 = 0;
#pragma unroll
        for (int e = 1; e < N_EXP; e++) if (l[e] > l[i0]) i0 = e;
        int i1 = (i0 == 0) ? 1 : 0;
#pragma unroll
        for (int e = 0; e < N_EXP; e++) if (e != i0 && l[e] > l[i1]) i1 = e;
        // renormalized top-2: softmax denominator cancels
        float r = __expf(l[i1] - l[i0]);
        float w0 = 1.f / (1.f + r);
        float w1 = r / (1.f + r);
        g_route_e[2 * t] = i0;  g_route_w[2 * t] = w0;
        g_route_e[2 * t + 1] = i1; g_route_w[2 * t + 1] = w1;
        atomicAdd(&g_cnt[i0], 1);
        atomicAdd(&g_cnt[i1], 1);
    }
}

__global__ void k_scan() {
    if (blockIdx.x == 0 && threadIdx.x == 0) {
        int off = 0;
        for (int e = 0; e < N_EXP; e++) { g_off[e] = off; off += g_cnt[e]; g_cur[e] = 0; }
        g_off[N_EXP] = off;
        int nt = 0;
        for (int e = 0; e < N_EXP; e++) {
            int c = g_cnt[e], r0 = g_off[e];
            int m = (c + BM - 1) / BM;
            for (int i = 0; i < m; i++) {
                g_tile_e[nt] = e;
                g_tile_r0[nt] = r0 + i * BM;
                g_tile_rend[nt] = r0 + c;
                nt++;
            }
        }
        g_ntiles = nt;
    }
}

__global__ void k_scatter() {
    int t = blockIdx.x * blockDim.x + threadIdx.x;
    if (t < T_TOK) {
#pragma unroll
        for (int k = 0; k < 2; k++) {
            int e = g_route_e[2 * t + k];
            int p = g_off[e] + atomicAdd(&g_cur[e], 1);
            g_rowtok[p] = t;
            g_roww[p] = g_route_w[2 * t + k];
        }
    }
}

// ---------------- GEMM1: H = silu(Xg @ W1) * (Xg @ W3), fused, tf32 ----------------
// block tile: 128 (rows) x 64 (cols, for BOTH w1 and w3) x K=1024
__global__ __launch_bounds__(256, 2)
void k_gemm1(const float* __restrict__ x, const float* __restrict__ w1g,
             const float* __restrict__ w3g) {
    int tile = blockIdx.x;
    if (tile >= g_ntiles) return;
    int e = g_tile_e[tile], row0 = g_tile_r0[tile], rend = g_tile_rend[tile];
    int n0 = blockIdx.y * 64;

    __shared__ float sA[BM][36];          // [m][k], stride 36 -> conflict-free frag loads
    __shared__ float sB[2][BK][68];       // [mat][k][n], stride 68
    __shared__ int   sTok[BM];

    int tid = threadIdx.x;
    if (tid < BM) {
        int r = row0 + tid;
        sTok[tid] = (r < rend) ? g_rowtok[r] : -1;
    }
    __syncthreads();

    const float* wb0 = w1g + (size_t)e * D_DIM * F_DIM;
    const float* wb1 = w3g + (size_t)e * D_DIM * F_DIM;

    int wid = tid >> 5, lane = tid & 31;
    int wm = (wid & 3) * 32, wn = (wid >> 2) * 32;

    float accP[2][4][4], accQ[2][4][4];
#pragma unroll
    for (int i = 0; i < 2; i++)
#pragma unroll
        for (int j = 0; j < 4; j++)
#pragma unroll
            for (int k = 0; k < 4; k++) { accP[i][j][k] = 0.f; accQ[i][j][k] = 0.f; }

    for (int kt = 0; kt < D_DIM / BK; kt++) {
        // A tile: 128x32 fp32, gathered rows
#pragma unroll
        for (int i = 0; i < 4; i++) {
            int idx = i * 256 + tid;       // 0..1023 float4 slots
            int row = idx >> 3, c4 = idx & 7;
            int tok = sTok[row];
            float4 v = make_float4(0.f, 0.f, 0.f, 0.f);
            if (tok >= 0)
                v = *(const float4*)(x + (size_t)tok * D_DIM + kt * BK + c4 * 4);
            float4 w = make_float4(f2tf(v.x), f2tf(v.y), f2tf(v.z), f2tf(v.w));
            *(float4*)&sA[row][c4 * 4] = w;
        }
        // B tiles: 32x64 for each of w1, w3
#pragma unroll
        for (int m = 0; m < 2; m++) {
            const float* wb = m ? wb1 : wb0;
#pragma unroll
            for (int i = 0; i < 2; i++) {
                int idx = i * 256 + tid;   // 0..511
                int kr = idx >> 4, c4 = idx & 15;
                float4 v = *(const float4*)(wb + (size_t)(kt * BK + kr) * F_DIM + n0 + c4 * 4);
                float4 w = make_float4(f2tf(v.x), f2tf(v.y), f2tf(v.z), f2tf(v.w));
                *(float4*)&sB[m][kr][c4 * 4] = w;
            }
        }
        __syncthreads();

#pragma unroll
        for (int ks = 0; ks < 4; ks++) {
            int kk = ks * 8;
            uint32_t a[2][4];
#pragma unroll
            for (int mf = 0; mf < 2; mf++) {
                int rb = wm + mf * 16;
                a[mf][0] = __float_as_uint(sA[rb + (lane >> 2)][kk + (lane & 3)]);
                a[mf][1] = __float_as_uint(sA[rb + 8 + (lane >> 2)][kk + (lane & 3)]);
                a[mf][2] = __float_as_uint(sA[rb + (lane >> 2)][kk + 4 + (lane & 3)]);
                a[mf][3] = __float_as_uint(sA[rb + 8 + (lane >> 2)][kk + 4 + (lane & 3)]);
            }
#pragma unroll
            for (int nf = 0; nf < 4; nf++) {
                int cb = wn + nf * 8 + (lane >> 2);
                uint32_t p0 = __float_as_uint(sB[0][kk + (lane & 3)][cb]);
                uint32_t p1 = __float_as_uint(sB[0][kk + 4 + (lane & 3)][cb]);
                uint32_t q0 = __float_as_uint(sB[1][kk + (lane & 3)][cb]);
                uint32_t q1 = __float_as_uint(sB[1][kk + 4 + (lane & 3)][cb]);
#pragma unroll
                for (int mf = 0; mf < 2; mf++) {
                    mma_tf32(accP[mf][nf], a[mf][0], a[mf][1], a[mf][2], a[mf][3], p0, p1);
                    mma_tf32(accQ[mf][nf], a[mf][0], a[mf][1], a[mf][2], a[mf][3], q0, q1);
                }
            }
        }
        __syncthreads();
    }

    // epilogue: h = silu(p) * q, fp32 store
#pragma unroll
    for (int mf = 0; mf < 2; mf++) {
#pragma unroll
        for (int half = 0; half < 2; half++) {
            int rl = wm + mf * 16 + (lane >> 2) + half * 8;
            int r = row0 + rl;
            if (r < rend) {
#pragma unroll
                for (int nf = 0; nf < 4; nf++) {
                    int col = n0 + wn + nf * 8 + (lane & 3) * 2;
                    float p0 = accP[mf][nf][half * 2], p1 = accP[mf][nf][half * 2 + 1];
                    float q0 = accQ[mf][nf][half * 2], q1 = accQ[mf][nf][half * 2 + 1];
                    float h0 = (p0 / (1.f + __expf(-p0))) * q0;
                    float h1 = (p1 / (1.f + __expf(-p1))) * q1;
                    *(float2*)(g_h + (size_t)r * F_DIM + col) = make_float2(h0, h1);
                }
            }
        }
    }
}

// ---------------- GEMM2: Y = H @ W2[e], scaled scatter-add into out ----------------
// block tile: 128 x 128 x K=3584
__global__ __launch_bounds__(256, 2)
void k_gemm2(const float* __restrict__ w2g, float* __restrict__ out) {
    int tile = blockIdx.x;
    if (tile >= g_ntiles) return;
    int e = g_tile_e[tile], row0 = g_tile_r0[tile], rend = g_tile_rend[tile];
    int n0 = blockIdx.y * 128;

    __shared__ float sA[BM][36];
    __shared__ float sB[BK][132];
    __shared__ int   sTok[BM];
    __shared__ float sW[BM];

    int tid = threadIdx.x;
    if (tid < BM) {
        int r = row0 + tid;
        sTok[tid] = (r < rend) ? g_rowtok[r] : 0;
        sW[tid]   = (r < rend) ? g_roww[r] : 0.f;
    }
    __syncthreads();

    const float* wb = w2g + (size_t)e * F_DIM * D_DIM;
    int wid = tid >> 5, lane = tid & 31;
    int wm = (wid & 1) * 64, wn = (wid >> 1) * 32;

    float acc[4][4][4];
#pragma unroll
    for (int i = 0; i < 4; i++)
#pragma unroll
        for (int j = 0; j < 4; j++)
#pragma unroll
            for (int k = 0; k < 4; k++) acc[i][j][k] = 0.f;

    for (int kt = 0; kt < F_DIM / BK; kt++) {
        // A: 128x32 from g_h (rows contiguous per segment)
#pragma unroll
        for (int i = 0; i < 4; i++) {
            int idx = i * 256 + tid;
            int row = idx >> 3, c4 = idx & 7;
            int r = row0 + row;
            float4 v = make_float4(0.f, 0.f, 0.f, 0.f);
            if (r < rend)
                v = *(const float4*)(g_h + (size_t)r * F_DIM + kt * BK + c4 * 4);
            float4 w = make_float4(f2tf(v.x), f2tf(v.y), f2tf(v.z), f2tf(v.w));
            *(float4*)&sA[row][c4 * 4] = w;
        }
        // B: 32x128 from w2
#pragma unroll
        for (int i = 0; i < 4; i++) {
            int idx = i * 256 + tid;
            int kr = idx >> 5, c4 = idx & 31;
            float4 v = *(const float4*)(wb + (size_t)(kt * BK + kr) * D_DIM + n0 + c4 * 4);
            float4 w = make_float4(f2tf(v.x), f2tf(v.y), f2tf(v.z), f2tf(v.w));
            *(float4*)&sB[kr][c4 * 4] = w;
        }
        __syncthreads();

#pragma unroll
        for (int ks = 0; ks < 4; ks++) {
            int kk = ks * 8;
            uint32_t a[4][4];
#pragma unroll
            for (int mf = 0; mf < 4; mf++) {
                int rb = wm + mf * 16;
                a[mf][0] = __float_as_uint(sA[rb + (lane >> 2)][kk + (lane & 3)]);
                a[mf][1] = __float_as_uint(sA[rb + 8 + (lane >> 2)][kk + (lane & 3)]);
                a[mf][2] = __float_as_uint(sA[rb + (lane >> 2)][kk + 4 + (lane & 3)]);
                a[mf][3] = __float_as_uint(sA[rb + 8 + (lane >> 2)][kk + 4 + (lane & 3)]);
            }
#pragma unroll
            for (int nf = 0; nf < 4; nf++) {
                int cb = wn + nf * 8 + (lane >> 2);
                uint32_t b0 = __float_as_uint(sB[kk + (lane & 3)][cb]);
                uint32_t b1 = __float_as_uint(sB[kk + 4 + (lane & 3)][cb]);
#pragma unroll
                for (int mf = 0; mf < 4; mf++)
                    mma_tf32(acc[mf][nf], a[mf][0], a[mf][1], a[mf][2], a[mf][3], b0, b1);
            }
        }
        __syncthreads();
    }

    // epilogue: out[tok, col] += weight * acc  (exactly 2 adds per element -> deterministic)
#pragma unroll
    for (int mf = 0; mf < 4; mf++) {
#pragma unroll
        for (int half = 0; half < 2; half++) {
            int rl = wm + mf * 16 + (lane >> 2) + half * 8;
            int r = row0 + rl;
            if (r < rend) {
                int tok = sTok[rl];
                float s = sW[rl];
                float* op = out + (size_t)tok * D_DIM;
#pragma unroll
                for (int nf = 0; nf < 4; nf++) {
                    int col = n0 + wn + nf * 8 + (lane & 3) * 2;
                    atomicAdd(op + col,     acc[mf][nf][half * 2] * s);
                    atomicAdd(op + col + 1, acc[mf][nf][half * 2 + 1] * s);
                }
            }
        }
    }
}

// ---------------- entry ----------------
extern "C" void kernel_launch(void* const* d_in, const int* in_sizes, int n_in,
                              void* d_out, int out_size) {
    const float* x  = (const float*)d_in[0];   // hidden_states [4,2048,1024]
    const float* gw = (const float*)d_in[1];   // gate_w [8,1024]
    const float* w1 = (const float*)d_in[2];   // [8,1024,3584]
    const float* w3 = (const float*)d_in[3];   // [8,1024,3584]
    const float* w2 = (const float*)d_in[4];   // [8,3584,1024]

    float* out = (float*)d_out;                         // [T*D] moe output
    float* logits = out + (size_t)T_TOK * D_DIM;        // [T*E] router logits

    k_reset<<<1, 32>>>();
    k_router<<<T_TOK, 256>>>(x, gw, logits);
    k_scan<<<1, 1>>>();
    k_scatter<<<T_TOK / 256, 256>>>();
    k_zero<<<2048, 256>>>((float4*)out, (T_TOK * D_DIM) / 4);

    dim3 g1(MAX_TILES, F_DIM / 64);
    k_gemm1<<<g1, 256>>>(x, w1, w3);

    dim3 g2(MAX_TILES, D_DIM / 128);
    k_gemm2<<<g2, 256>>>(w2, out);
}

// round 4
// speedup vs baseline: 1.9039x; 1.9039x over previous
#include <cuda_runtime.h>
#include <cuda_bf16.h>
#include <cstdint>

#define T_TOK 8192
#define D_DIM 1024
#define F_DIM 3584
#define N_EXP 8
#define N_ASSIGN (T_TOK * 2)            // 16384 expert assignments
#define BM 128
#define BK 32
#define MAX_TILES (N_ASSIGN / BM + N_EXP)  // 136

// ---------------- scratch (static __device__, allocation-free) ----------------
__device__ float g_h[(size_t)N_ASSIGN * F_DIM];   // intermediate SwiGLU output (fp32)
__device__ int   g_rowtok[N_ASSIGN];
__device__ float g_roww[N_ASSIGN];
__device__ int   g_route_e[N_ASSIGN];
__device__ float g_route_w[N_ASSIGN];
__device__ int   g_cnt[N_EXP];
__device__ int   g_cur[N_EXP];
__device__ int   g_off[N_EXP + 1];
__device__ int   g_tile_e[MAX_TILES];
__device__ int   g_tile_r0[MAX_TILES];
__device__ int   g_tile_rend[MAX_TILES];
__device__ int   g_ntiles;

// ---------------- helpers ----------------
__device__ __forceinline__ uint32_t f2tfu(float f) {
    // round-to-nearest tf32 (unbiased) — raw truncation would bias result ~1e-3
    uint32_t r;
    asm("cvt.rna.tf32.f32 %0, %1;" : "=r"(r) : "f"(f));
    return r;
}

__device__ __forceinline__ void mma_tf32(float c[4], uint32_t a0, uint32_t a1,
                                         uint32_t a2, uint32_t a3,
                                         uint32_t b0, uint32_t b1) {
    asm volatile(
        "mma.sync.aligned.m16n8k8.row.col.f32.tf32.tf32.f32 "
        "{%0,%1,%2,%3}, {%4,%5,%6,%7}, {%8,%9}, {%0,%1,%2,%3};\n"
        : "+f"(c[0]), "+f"(c[1]), "+f"(c[2]), "+f"(c[3])
        : "r"(a0), "r"(a1), "r"(a2), "r"(a3), "r"(b0), "r"(b1));
}

// cp.async 16B: always-on and predicated (pred=false -> zero-fill 16B)
__device__ __forceinline__ void cp16(void* s, const void* g) {
    uint32_t sa = (uint32_t)__cvta_generic_to_shared(s);
    asm volatile("cp.async.cg.shared.global [%0], [%1], 16;\n" :: "r"(sa), "l"(g));
}
__device__ __forceinline__ void cp16p(void* s, const void* g, bool p) {
    uint32_t sa = (uint32_t)__cvta_generic_to_shared(s);
    int b = p ? 16 : 0;
    asm volatile("cp.async.cg.shared.global [%0], [%1], 16, %2;\n" :: "r"(sa), "l"(g), "r"(b));
}
__device__ __forceinline__ void cp_commit() {
    asm volatile("cp.async.commit_group;\n" ::: "memory");
}
template <int N>
__device__ __forceinline__ void cp_wait() {
    asm volatile("cp.async.wait_group %0;\n" :: "n"(N) : "memory");
}

// ---------------- small kernels ----------------
__global__ void k_reset() {
    int i = threadIdx.x;
    if (i < N_EXP) { g_cnt[i] = 0; g_cur[i] = 0; }
}

__global__ void k_zero(float4* p, int n4) {
    int stride = gridDim.x * blockDim.x;
    for (int i = blockIdx.x * blockDim.x + threadIdx.x; i < n4; i += stride)
        p[i] = make_float4(0.f, 0.f, 0.f, 0.f);
}

__global__ void k_router(const float* __restrict__ x, const float* __restrict__ gw,
                         float* __restrict__ logits_out) {
    int t = blockIdx.x;
    int tid = threadIdx.x;                 // 256 threads
    const float* xr = x + (size_t)t * D_DIM;

    float acc[N_EXP];
#pragma unroll
    for (int e = 0; e < N_EXP; e++) acc[e] = 0.f;

    for (int j = tid; j < D_DIM; j += 256) {
        float xv = xr[j];
#pragma unroll
        for (int e = 0; e < N_EXP; e++) acc[e] += xv * gw[e * D_DIM + j];
    }
#pragma unroll
    for (int e = 0; e < N_EXP; e++)
#pragma unroll
        for (int o = 16; o > 0; o >>= 1)
            acc[e] += __shfl_xor_sync(0xffffffffu, acc[e], o);

    __shared__ float wsum[8][N_EXP];
    __shared__ float sl[N_EXP];
    int wid = tid >> 5, lane = tid & 31;
    if (lane == 0) {
#pragma unroll
        for (int e = 0; e < N_EXP; e++) wsum[wid][e] = acc[e];
    }
    __syncthreads();
    if (tid < N_EXP) {
        float s = 0.f;
#pragma unroll
        for (int w = 0; w < 8; w++) s += wsum[w][tid];
        sl[tid] = s;
        logits_out[(size_t)t * N_EXP + tid] = s;   // raw router logits output
    }
    __syncthreads();
    if (tid == 0) {
        float l[N_EXP];
#pragma unroll
        for (int e = 0; e < N_EXP; e++) l[e] = sl[e];
        int i0 = 0;
#pragma unroll
        for (int e = 1; e < N_EXP; e++) if (l[e] > l[i0]) i0 = e;
        int i1 = (i0 == 0) ? 1 : 0;
#pragma unroll
        for (int e = 0; e < N_EXP; e++) if (e != i0 && l[e] > l[i1]) i1 = e;
        // renormalized top-2: softmax denominator cancels
        float r = __expf(l[i1] - l[i0]);
        float w0 = 1.f / (1.f + r);
        float w1 = r / (1.f + r);
        g_route_e[2 * t] = i0;  g_route_w[2 * t] = w0;
        g_route_e[2 * t + 1] = i1; g_route_w[2 * t + 1] = w1;
        atomicAdd(&g_cnt[i0], 1);
        atomicAdd(&g_cnt[i1], 1);
    }
}

__global__ void k_scan() {
    if (blockIdx.x == 0 && threadIdx.x == 0) {
        int off = 0;
        for (int e = 0; e < N_EXP; e++) { g_off[e] = off; off += g_cnt[e]; g_cur[e] = 0; }
        g_off[N_EXP] = off;
        int nt = 0;
        for (int e = 0; e < N_EXP; e++) {
            int c = g_cnt[e], r0 = g_off[e];
            int m = (c + BM - 1) / BM;
            for (int i = 0; i < m; i++) {
                g_tile_e[nt] = e;
                g_tile_r0[nt] = r0 + i * BM;
                g_tile_rend[nt] = r0 + c;
                nt++;
            }
        }
        g_ntiles = nt;
    }
}

__global__ void k_scatter() {
    int t = blockIdx.x * blockDim.x + threadIdx.x;
    if (t < T_TOK) {
#pragma unroll
        for (int k = 0; k < 2; k++) {
            int e = g_route_e[2 * t + k];
            int p = g_off[e] + atomicAdd(&g_cur[e], 1);
            g_rowtok[p] = t;
            g_roww[p] = g_route_w[2 * t + k];
        }
    }
}

// ---------------- GEMM1: H = silu(Xg @ W1) * (Xg @ W3), fused, tf32 ----------------
// block tile: 128 (rows) x 64 (cols, for BOTH w1 and w3) x K=1024
// 2-stage cp.async pipeline; smem (dynamic): A[2][128][36] + B[2][2][32][68]
#define G1_SMEM ((2 * 128 * 36 + 2 * 2 * 32 * 68) * 4)
__global__ __launch_bounds__(256, 2)
void k_gemm1(const float* __restrict__ x, const float* __restrict__ w1g,
             const float* __restrict__ w3g) {
    int tile = blockIdx.x;
    if (tile >= g_ntiles) return;
    int e = g_tile_e[tile], row0 = g_tile_r0[tile], rend = g_tile_rend[tile];
    int n0 = blockIdx.y * 64;

    extern __shared__ float dyn[];
    float (*sA)[BM][36]     = (float (*)[BM][36])dyn;                 // [2][128][36]
    float (*sB)[2][BK][68]  = (float (*)[2][BK][68])(dyn + 2 * BM * 36);

    __shared__ int sTok[BM];

    int tid = threadIdx.x;
    if (tid < BM) {
        int r = row0 + tid;
        sTok[tid] = (r < rend) ? g_rowtok[r] : -1;
    }
    __syncthreads();

    const float* wb0 = w1g + (size_t)e * D_DIM * F_DIM;
    const float* wb1 = w3g + (size_t)e * D_DIM * F_DIM;

    int wid = tid >> 5, lane = tid & 31;
    int wm = (wid & 3) * 32, wn = (wid >> 2) * 32;

    // per-thread load coordinates (fixed across k-tiles)
    int arow[4], ac4[4];
    const float* asrc[4];
#pragma unroll
    for (int i = 0; i < 4; i++) {
        int idx = i * 256 + tid;           // 0..1023 float4 slots
        arow[i] = idx >> 3; ac4[i] = idx & 7;
        int tok = sTok[arow[i]];
        asrc[i] = (tok >= 0) ? (x + (size_t)tok * D_DIM + ac4[i] * 4) : x;
    }
    bool apred[4];
#pragma unroll
    for (int i = 0; i < 4; i++) apred[i] = (sTok[arow[i]] >= 0);

    // issue k-tile kt into buffer buf
    auto issue = [&](int kt, int buf) {
#pragma unroll
        for (int i = 0; i < 4; i++)
            cp16p(&sA[buf][arow[i]][ac4[i] * 4], asrc[i] + kt * BK, apred[i]);
#pragma unroll
        for (int m = 0; m < 2; m++) {
            const float* wb = m ? wb1 : wb0;
#pragma unroll
            for (int i = 0; i < 2; i++) {
                int idx = i * 256 + tid;   // 0..511
                int kr = idx >> 4, c4 = idx & 15;
                cp16(&sB[buf][m][kr][c4 * 4],
                     wb + (size_t)(kt * BK + kr) * F_DIM + n0 + c4 * 4);
            }
        }
        cp_commit();
    };

    float accP[2][4][4], accQ[2][4][4];
#pragma unroll
    for (int i = 0; i < 2; i++)
#pragma unroll
        for (int j = 0; j < 4; j++)
#pragma unroll
            for (int k = 0; k < 4; k++) { accP[i][j][k] = 0.f; accQ[i][j][k] = 0.f; }

    const int NK = D_DIM / BK;             // 32
    issue(0, 0);

    for (int kt = 0; kt < NK; kt++) {
        int buf = kt & 1;
        if (kt + 1 < NK) { issue(kt + 1, (kt + 1) & 1); cp_wait<1>(); }
        else             { cp_wait<0>(); }
        __syncthreads();

#pragma unroll
        for (int ks = 0; ks < 4; ks++) {
            int kk = ks * 8;
            uint32_t a[2][4];
#pragma unroll
            for (int mf = 0; mf < 2; mf++) {
                int rb = wm + mf * 16;
                a[mf][0] = f2tfu(sA[buf][rb + (lane >> 2)][kk + (lane & 3)]);
                a[mf][1] = f2tfu(sA[buf][rb + 8 + (lane >> 2)][kk + (lane & 3)]);
                a[mf][2] = f2tfu(sA[buf][rb + (lane >> 2)][kk + 4 + (lane & 3)]);
                a[mf][3] = f2tfu(sA[buf][rb + 8 + (lane >> 2)][kk + 4 + (lane & 3)]);
            }
#pragma unroll
            for (int nf = 0; nf < 4; nf++) {
                int cb = wn + nf * 8 + (lane >> 2);
                uint32_t p0 = f2tfu(sB[buf][0][kk + (lane & 3)][cb]);
                uint32_t p1 = f2tfu(sB[buf][0][kk + 4 + (lane & 3)][cb]);
                uint32_t q0 = f2tfu(sB[buf][1][kk + (lane & 3)][cb]);
                uint32_t q1 = f2tfu(sB[buf][1][kk + 4 + (lane & 3)][cb]);
#pragma unroll
                for (int mf = 0; mf < 2; mf++) {
                    mma_tf32(accP[mf][nf], a[mf][0], a[mf][1], a[mf][2], a[mf][3], p0, p1);
                    mma_tf32(accQ[mf][nf], a[mf][0], a[mf][1], a[mf][2], a[mf][3], q0, q1);
                }
            }
        }
        __syncthreads();
    }

    // epilogue: h = silu(p) * q, fp32 store
#pragma unroll
    for (int mf = 0; mf < 2; mf++) {
#pragma unroll
        for (int half = 0; half < 2; half++) {
            int rl = wm + mf * 16 + (lane >> 2) + half * 8;
            int r = row0 + rl;
            if (r < rend) {
#pragma unroll
                for (int nf = 0; nf < 4; nf++) {
                    int col = n0 + wn + nf * 8 + (lane & 3) * 2;
                    float p0 = accP[mf][nf][half * 2], p1 = accP[mf][nf][half * 2 + 1];
                    float q0 = accQ[mf][nf][half * 2], q1 = accQ[mf][nf][half * 2 + 1];
                    float h0 = (p0 / (1.f + __expf(-p0))) * q0;
                    float h1 = (p1 / (1.f + __expf(-p1))) * q1;
                    *(float2*)(g_h + (size_t)r * F_DIM + col) = make_float2(h0, h1);
                }
            }
        }
    }
}

// ---------------- GEMM2: Y = H @ W2[e], scaled scatter-add into out ----------------
// block tile: 128 x 128 x K=3584, 2-stage cp.async pipeline
// smem (dynamic): A[2][128][36] + B[2][32][132]
#define G2_SMEM ((2 * 128 * 36 + 2 * 32 * 132) * 4)
__global__ __launch_bounds__(256, 2)
void k_gemm2(const float* __restrict__ w2g, float* __restrict__ out) {
    int tile = blockIdx.x;
    if (tile >= g_ntiles) return;
    int e = g_tile_e[tile], row0 = g_tile_r0[tile], rend = g_tile_rend[tile];
    int n0 = blockIdx.y * 128;

    extern __shared__ float dyn[];
    float (*sA)[BM][36]  = (float (*)[BM][36])dyn;                    // [2][128][36]
    float (*sB)[BK][132] = (float (*)[BK][132])(dyn + 2 * BM * 36);   // [2][32][132]

    __shared__ int   sTok[BM];
    __shared__ float sW[BM];

    int tid = threadIdx.x;
    if (tid < BM) {
        int r = row0 + tid;
        sTok[tid] = (r < rend) ? g_rowtok[r] : 0;
        sW[tid]   = (r < rend) ? g_roww[r] : 0.f;
    }
    __syncthreads();

    const float* wb = w2g + (size_t)e * F_DIM * D_DIM;
    int wid = tid >> 5, lane = tid & 31;
    int wm = (wid & 1) * 64, wn = (wid >> 1) * 32;

    int arow[4], ac4[4];
    bool apred[4];
#pragma unroll
    for (int i = 0; i < 4; i++) {
        int idx = i * 256 + tid;
        arow[i] = idx >> 3; ac4[i] = idx & 7;
        apred[i] = (row0 + arow[i]) < rend;
    }

    auto issue = [&](int kt, int buf) {
#pragma unroll
        for (int i = 0; i < 4; i++)
            cp16p(&sA[buf][arow[i]][ac4[i] * 4],
                  g_h + (size_t)(row0 + arow[i]) * F_DIM + kt * BK + ac4[i] * 4,
                  apred[i]);
#pragma unroll
        for (int i = 0; i < 4; i++) {
            int idx = i * 256 + tid;
            int kr = idx >> 5, c4 = idx & 31;
            cp16(&sB[buf][kr][c4 * 4],
                 wb + (size_t)(kt * BK + kr) * D_DIM + n0 + c4 * 4);
        }
        cp_commit();
    };

    float acc[4][4][4];
#pragma unroll
    for (int i = 0; i < 4; i++)
#pragma unroll
        for (int j = 0; j < 4; j++)
#pragma unroll
            for (int k = 0; k < 4; k++) acc[i][j][k] = 0.f;

    const int NK = F_DIM / BK;             // 112
    issue(0, 0);

    for (int kt = 0; kt < NK; kt++) {
        int buf = kt & 1;
        if (kt + 1 < NK) { issue(kt + 1, (kt + 1) & 1); cp_wait<1>(); }
        else             { cp_wait<0>(); }
        __syncthreads();

#pragma unroll
        for (int ks = 0; ks < 4; ks++) {
            int kk = ks * 8;
            uint32_t a[4][4];
#pragma unroll
            for (int mf = 0; mf < 4; mf++) {
                int rb = wm + mf * 16;
                a[mf][0] = f2tfu(sA[buf][rb + (lane >> 2)][kk + (lane & 3)]);
                a[mf][1] = f2tfu(sA[buf][rb + 8 + (lane >> 2)][kk + (lane & 3)]);
                a[mf][2] = f2tfu(sA[buf][rb + (lane >> 2)][kk + 4 + (lane & 3)]);
                a[mf][3] = f2tfu(sA[buf][rb + 8 + (lane >> 2)][kk + 4 + (lane & 3)]);
            }
#pragma unroll
            for (int nf = 0; nf < 4; nf++) {
                int cb = wn + nf * 8 + (lane >> 2);
                uint32_t b0 = f2tfu(sB[buf][kk + (lane & 3)][cb]);
                uint32_t b1 = f2tfu(sB[buf][kk + 4 + (lane & 3)][cb]);
#pragma unroll
                for (int mf = 0; mf < 4; mf++)
                    mma_tf32(acc[mf][nf], a[mf][0], a[mf][1], a[mf][2], a[mf][3], b0, b1);
            }
        }
        __syncthreads();
    }

    // epilogue: out[tok, col] += weight * acc  (exactly 2 adds per element -> deterministic)
#pragma unroll
    for (int mf = 0; mf < 4; mf++) {
#pragma unroll
        for (int half = 0; half < 2; half++) {
            int rl = wm + mf * 16 + (lane >> 2) + half * 8;
            int r = row0 + rl;
            if (r < rend) {
                int tok = sTok[rl];
                float s = sW[rl];
                float* op = out + (size_t)tok * D_DIM;
#pragma unroll
                for (int nf = 0; nf < 4; nf++) {
                    int col = n0 + wn + nf * 8 + (lane & 3) * 2;
                    atomicAdd(op + col,     acc[mf][nf][half * 2] * s);
                    atomicAdd(op + col + 1, acc[mf][nf][half * 2 + 1] * s);
                }
            }
        }
    }
}

// ---------------- entry ----------------
extern "C" void kernel_launch(void* const* d_in, const int* in_sizes, int n_in,
                              void* d_out, int out_size) {
    const float* x  = (const float*)d_in[0];   // hidden_states [4,2048,1024]
    const float* gw = (const float*)d_in[1];   // gate_w [8,1024]
    const float* w1 = (const float*)d_in[2];   // [8,1024,3584]
    const float* w3 = (const float*)d_in[3];   // [8,1024,3584]
    const float* w2 = (const float*)d_in[4];   // [8,3584,1024]

    float* out = (float*)d_out;                         // [T*D] moe output
    float* logits = out + (size_t)T_TOK * D_DIM;        // [T*E] router logits

    static bool attr_set = false;
    if (!attr_set) {
        cudaFuncSetAttribute(k_gemm1, cudaFuncAttributeMaxDynamicSharedMemorySize, G1_SMEM);
        cudaFuncSetAttribute(k_gemm2, cudaFuncAttributeMaxDynamicSharedMemorySize, G2_SMEM);
        attr_set = true;
    }

    k_reset<<<1, 32>>>();
    k_router<<<T_TOK, 256>>>(x, gw, logits);
    k_scan<<<1, 1>>>();
    k_scatter<<<T_TOK / 256, 256>>>();
    k_zero<<<2048, 256>>>((float4*)out, (T_TOK * D_DIM) / 4);

    dim3 g1(MAX_TILES, F_DIM / 64);
    k_gemm1<<<g1, 256, G1_SMEM>>>(x, w1, w3);

    dim3 g2(MAX_TILES, D_DIM / 128);
    k_gemm2<<<g2, 256, G2_SMEM>>>(w2, out);
}

// round 5
// speedup vs baseline: 1.9052x; 1.0007x over previous
#include <cuda_runtime.h>
#include <cuda_bf16.h>
#include <cstdint>

#define T_TOK 8192
#define D_DIM 1024
#define F_DIM 3584
#define N_EXP 8
#define N_ASSIGN (T_TOK * 2)            // 16384 expert assignments
#define BM 128
#define BK 32
#define MAX_TILES (N_ASSIGN / BM + N_EXP)  // 136

// ---------------- scratch (static __device__, allocation-free) ----------------
__device__ float g_h[(size_t)N_ASSIGN * F_DIM];   // intermediate SwiGLU output (fp32)
__device__ int   g_rowtok[N_ASSIGN];
__device__ float g_roww[N_ASSIGN];
__device__ int   g_route_e[N_ASSIGN];
__device__ float g_route_w[N_ASSIGN];
__device__ int   g_cnt[N_EXP];
__device__ int   g_cur[N_EXP];
__device__ int   g_off[N_EXP + 1];
__device__ int   g_tile_e[MAX_TILES];
__device__ int   g_tile_r0[MAX_TILES];
__device__ int   g_tile_rend[MAX_TILES];
__device__ int   g_ntiles;

// ---------------- helpers ----------------
__device__ __forceinline__ uint32_t f2tfu(float f) {
    // round-to-nearest tf32 (unbiased) — raw truncation would bias result ~1e-3
    uint32_t r;
    asm("cvt.rna.tf32.f32 %0, %1;" : "=r"(r) : "f"(f));
    return r;
}

__device__ __forceinline__ void mma_tf32(float c[4], uint32_t a0, uint32_t a1,
                                         uint32_t a2, uint32_t a3,
                                         uint32_t b0, uint32_t b1) {
    asm volatile(
        "mma.sync.aligned.m16n8k8.row.col.f32.tf32.tf32.f32 "
        "{%0,%1,%2,%3}, {%4,%5,%6,%7}, {%8,%9}, {%0,%1,%2,%3};\n"
        : "+f"(c[0]), "+f"(c[1]), "+f"(c[2]), "+f"(c[3])
        : "r"(a0), "r"(a1), "r"(a2), "r"(a3), "r"(b0), "r"(b1));
}

// cp.async 16B: always-on and predicated (pred=false -> zero-fill 16B)
__device__ __forceinline__ void cp16(void* s, const void* g) {
    uint32_t sa = (uint32_t)__cvta_generic_to_shared(s);
    asm volatile("cp.async.cg.shared.global [%0], [%1], 16;\n" :: "r"(sa), "l"(g));
}
__device__ __forceinline__ void cp16p(void* s, const void* g, bool p) {
    uint32_t sa = (uint32_t)__cvta_generic_to_shared(s);
    int b = p ? 16 : 0;
    asm volatile("cp.async.cg.shared.global [%0], [%1], 16, %2;\n" :: "r"(sa), "l"(g), "r"(b));
}
__device__ __forceinline__ void cp_commit() {
    asm volatile("cp.async.commit_group;\n" ::: "memory");
}
template <int N>
__device__ __forceinline__ void cp_wait() {
    asm volatile("cp.async.wait_group %0;\n" :: "n"(N) : "memory");
}

// ---------------- small kernels ----------------
__global__ void k_reset() {
    int i = threadIdx.x;
    if (i < N_EXP) { g_cnt[i] = 0; g_cur[i] = 0; }
}

__global__ void k_zero(float4* p, int n4) {
    int stride = gridDim.x * blockDim.x;
    for (int i = blockIdx.x * blockDim.x + threadIdx.x; i < n4; i += stride)
        p[i] = make_float4(0.f, 0.f, 0.f, 0.f);
}

__global__ void k_router(const float* __restrict__ x, const float* __restrict__ gw,
                         float* __restrict__ logits_out) {
    int t = blockIdx.x;
    int tid = threadIdx.x;                 // 256 threads
    const float* xr = x + (size_t)t * D_DIM;

    float acc[N_EXP];
#pragma unroll
    for (int e = 0; e < N_EXP; e++) acc[e] = 0.f;

    for (int j = tid; j < D_DIM; j += 256) {
        float xv = xr[j];
#pragma unroll
        for (int e = 0; e < N_EXP; e++) acc[e] += xv * gw[e * D_DIM + j];
    }
#pragma unroll
    for (int e = 0; e < N_EXP; e++)
#pragma unroll
        for (int o = 16; o > 0; o >>= 1)
            acc[e] += __shfl_xor_sync(0xffffffffu, acc[e], o);

    __shared__ float wsum[8][N_EXP];
    __shared__ float sl[N_EXP];
    int wid = tid >> 5, lane = tid & 31;
    if (lane == 0) {
#pragma unroll
        for (int e = 0; e < N_EXP; e++) wsum[wid][e] = acc[e];
    }
    __syncthreads();
    if (tid < N_EXP) {
        float s = 0.f;
#pragma unroll
        for (int w = 0; w < 8; w++) s += wsum[w][tid];
        sl[tid] = s;
        logits_out[(size_t)t * N_EXP + tid] = s;   // raw router logits output
    }
    __syncthreads();
    if (tid == 0) {
        float l[N_EXP];
#pragma unroll
        for (int e = 0; e < N_EXP; e++) l[e] = sl[e];
        int i0 = 0;
#pragma unroll
        for (int e = 1; e < N_EXP; e++) if (l[e] > l[i0]) i0 = e;
        int i1 = (i0 == 0) ? 1 : 0;
#pragma unroll
        for (int e = 0; e < N_EXP; e++) if (e != i0 && l[e] > l[i1]) i1 = e;
        // renormalized top-2: softmax denominator cancels
        float r = __expf(l[i1] - l[i0]);
        float w0 = 1.f / (1.f + r);
        float w1 = r / (1.f + r);
        g_route_e[2 * t] = i0;  g_route_w[2 * t] = w0;
        g_route_e[2 * t + 1] = i1; g_route_w[2 * t + 1] = w1;
        atomicAdd(&g_cnt[i0], 1);
        atomicAdd(&g_cnt[i1], 1);
    }
}

__global__ void k_scan() {
    if (blockIdx.x == 0 && threadIdx.x == 0) {
        int off = 0;
        for (int e = 0; e < N_EXP; e++) { g_off[e] = off; off += g_cnt[e]; g_cur[e] = 0; }
        g_off[N_EXP] = off;
        int nt = 0;
        for (int e = 0; e < N_EXP; e++) {
            int c = g_cnt[e], r0 = g_off[e];
            int m = (c + BM - 1) / BM;
            for (int i = 0; i < m; i++) {
                g_tile_e[nt] = e;
                g_tile_r0[nt] = r0 + i * BM;
                g_tile_rend[nt] = r0 + c;
                nt++;
            }
        }
        g_ntiles = nt;
    }
}

__global__ void k_scatter() {
    int t = blockIdx.x * blockDim.x + threadIdx.x;
    if (t < T_TOK) {
#pragma unroll
        for (int k = 0; k < 2; k++) {
            int e = g_route_e[2 * t + k];
            int p = g_off[e] + atomicAdd(&g_cur[e], 1);
            g_rowtok[p] = t;
            g_roww[p] = g_route_w[2 * t + k];
        }
    }
}

// ---------------- GEMM1: H = silu(Xg @ W1) * (Xg @ W3), fused, tf32 ----------------
// block tile: 128 (rows) x 64 (cols, for BOTH w1 and w3) x K=1024
// 2-stage cp.async pipeline; smem (dynamic): A[2][128][36] + B[2][2][32][68]
#define G1_SMEM ((2 * 128 * 36 + 2 * 2 * 32 * 68) * 4)
__global__ __launch_bounds__(256, 2)
void k_gemm1(const float* __restrict__ x, const float* __restrict__ w1g,
             const float* __restrict__ w3g) {
    int tile = blockIdx.x;
    if (tile >= g_ntiles) return;
    int e = g_tile_e[tile], row0 = g_tile_r0[tile], rend = g_tile_rend[tile];
    int n0 = blockIdx.y * 64;

    extern __shared__ float dyn[];
    float (*sA)[BM][36]     = (float (*)[BM][36])dyn;                 // [2][128][36]
    float (*sB)[2][BK][68]  = (float (*)[2][BK][68])(dyn + 2 * BM * 36);

    __shared__ int sTok[BM];

    int tid = threadIdx.x;
    if (tid < BM) {
        int r = row0 + tid;
        sTok[tid] = (r < rend) ? g_rowtok[r] : -1;
    }
    __syncthreads();

    const float* wb0 = w1g + (size_t)e * D_DIM * F_DIM;
    const float* wb1 = w3g + (size_t)e * D_DIM * F_DIM;

    int wid = tid >> 5, lane = tid & 31;
    int wm = (wid & 3) * 32, wn = (wid >> 2) * 32;

    // per-thread load coordinates (fixed across k-tiles)
    int arow[4], ac4[4];
    const float* asrc[4];
#pragma unroll
    for (int i = 0; i < 4; i++) {
        int idx = i * 256 + tid;           // 0..1023 float4 slots
        arow[i] = idx >> 3; ac4[i] = idx & 7;
        int tok = sTok[arow[i]];
        asrc[i] = (tok >= 0) ? (x + (size_t)tok * D_DIM + ac4[i] * 4) : x;
    }
    bool apred[4];
#pragma unroll
    for (int i = 0; i < 4; i++) apred[i] = (sTok[arow[i]] >= 0);

    // issue k-tile kt into buffer buf
    auto issue = [&](int kt, int buf) {
#pragma unroll
        for (int i = 0; i < 4; i++)
            cp16p(&sA[buf][arow[i]][ac4[i] * 4], asrc[i] + kt * BK, apred[i]);
#pragma unroll
        for (int m = 0; m < 2; m++) {
            const float* wb = m ? wb1 : wb0;
#pragma unroll
            for (int i = 0; i < 2; i++) {
                int idx = i * 256 + tid;   // 0..511
                int kr = idx >> 4, c4 = idx & 15;
                cp16(&sB[buf][m][kr][c4 * 4],
                     wb + (size_t)(kt * BK + kr) * F_DIM + n0 + c4 * 4);
            }
        }
        cp_commit();
    };

    float accP[2][4][4], accQ[2][4][4];
#pragma unroll
    for (int i = 0; i < 2; i++)
#pragma unroll
        for (int j = 0; j < 4; j++)
#pragma unroll
            for (int k = 0; k < 4; k++) { accP[i][j][k] = 0.f; accQ[i][j][k] = 0.f; }

    const int NK = D_DIM / BK;             // 32
    issue(0, 0);

    for (int kt = 0; kt < NK; kt++) {
        int buf = kt & 1;
        if (kt + 1 < NK) { issue(kt + 1, (kt + 1) & 1); cp_wait<1>(); }
        else             { cp_wait<0>(); }
        __syncthreads();

#pragma unroll
        for (int ks = 0; ks < 4; ks++) {
            int kk = ks * 8;
            uint32_t a[2][4];
#pragma unroll
            for (int mf = 0; mf < 2; mf++) {
                int rb = wm + mf * 16;
                a[mf][0] = f2tfu(sA[buf][rb + (lane >> 2)][kk + (lane & 3)]);
                a[mf][1] = f2tfu(sA[buf][rb + 8 + (lane >> 2)][kk + (lane & 3)]);
                a[mf][2] = f2tfu(sA[buf][rb + (lane >> 2)][kk + 4 + (lane & 3)]);
                a[mf][3] = f2tfu(sA[buf][rb + 8 + (lane >> 2)][kk + 4 + (lane & 3)]);
            }
#pragma unroll
            for (int nf = 0; nf < 4; nf++) {
                int cb = wn + nf * 8 + (lane >> 2);
                uint32_t p0 = f2tfu(sB[buf][0][kk + (lane & 3)][cb]);
                uint32_t p1 = f2tfu(sB[buf][0][kk + 4 + (lane & 3)][cb]);
                uint32_t q0 = f2tfu(sB[buf][1][kk + (lane & 3)][cb]);
                uint32_t q1 = f2tfu(sB[buf][1][kk + 4 + (lane & 3)][cb]);
#pragma unroll
                for (int mf = 0; mf < 2; mf++) {
                    mma_tf32(accP[mf][nf], a[mf][0], a[mf][1], a[mf][2], a[mf][3], p0, p1);
                    mma_tf32(accQ[mf][nf], a[mf][0], a[mf][1], a[mf][2], a[mf][3], q0, q1);
                }
            }
        }
        __syncthreads();
    }

    // epilogue: h = silu(p) * q, fp32 store
#pragma unroll
    for (int mf = 0; mf < 2; mf++) {
#pragma unroll
        for (int half = 0; half < 2; half++) {
            int rl = wm + mf * 16 + (lane >> 2) + half * 8;
            int r = row0 + rl;
            if (r < rend) {
#pragma unroll
                for (int nf = 0; nf < 4; nf++) {
                    int col = n0 + wn + nf * 8 + (lane & 3) * 2;
                    float p0 = accP[mf][nf][half * 2], p1 = accP[mf][nf][half * 2 + 1];
                    float q0 = accQ[mf][nf][half * 2], q1 = accQ[mf][nf][half * 2 + 1];
                    float h0 = (p0 / (1.f + __expf(-p0))) * q0;
                    float h1 = (p1 / (1.f + __expf(-p1))) * q1;
                    *(float2*)(g_h + (size_t)r * F_DIM + col) = make_float2(h0, h1);
                }
            }
        }
    }
}

// ---------------- GEMM2: Y = H @ W2[e], scaled scatter-add into out ----------------
// block tile: 128 x 128 x K=3584, 2-stage cp.async pipeline
// smem (dynamic): A[2][128][36] + B[2][32][132]
#define G2_SMEM ((2 * 128 * 36 + 2 * 32 * 132) * 4)
__global__ __launch_bounds__(256, 2)
void k_gemm2(const float* __restrict__ w2g, float* __restrict__ out) {
    int tile = blockIdx.x;
    if (tile >= g_ntiles) return;
    int e = g_tile_e[tile], row0 = g_tile_r0[tile], rend = g_tile_rend[tile];
    int n0 = blockIdx.y * 128;

    extern __shared__ float dyn[];
    float (*sA)[BM][36]  = (float (*)[BM][36])dyn;                    // [2][128][36]
    float (*sB)[BK][132] = (float (*)[BK][132])(dyn + 2 * BM * 36);   // [2][32][132]

    __shared__ int   sTok[BM];
    __shared__ float sW[BM];

    int tid = threadIdx.x;
    if (tid < BM) {
        int r = row0 + tid;
        sTok[tid] = (r < rend) ? g_rowtok[r] : 0;
        sW[tid]   = (r < rend) ? g_roww[r] : 0.f;
    }
    __syncthreads();

    const float* wb = w2g + (size_t)e * F_DIM * D_DIM;
    int wid = tid >> 5, lane = tid & 31;
    int wm = (wid & 1) * 64, wn = (wid >> 1) * 32;

    int arow[4], ac4[4];
    bool apred[4];
#pragma unroll
    for (int i = 0; i < 4; i++) {
        int idx = i * 256 + tid;
        arow[i] = idx >> 3; ac4[i] = idx & 7;
        apred[i] = (row0 + arow[i]) < rend;
    }

    auto issue = [&](int kt, int buf) {
#pragma unroll
        for (int i = 0; i < 4; i++)
            cp16p(&sA[buf][arow[i]][ac4[i] * 4],
                  g_h + (size_t)(row0 + arow[i]) * F_DIM + kt * BK + ac4[i] * 4,
                  apred[i]);
#pragma unroll
        for (int i = 0; i < 4; i++) {
            int idx = i * 256 + tid;
            int kr = idx >> 5, c4 = idx & 31;
            cp16(&sB[buf][kr][c4 * 4],
                 wb + (size_t)(kt * BK + kr) * D_DIM + n0 + c4 * 4);
        }
        cp_commit();
    };

    float acc[4][4][4];
#pragma unroll
    for (int i = 0; i < 4; i++)
#pragma unroll
        for (int j = 0; j < 4; j++)
#pragma unroll
            for (int k = 0; k < 4; k++) acc[i][j][k] = 0.f;

    const int NK = F_DIM / BK;             // 112
    issue(0, 0);

    for (int kt = 0; kt < NK; kt++) {
        int buf = kt & 1;
        if (kt + 1 < NK) { issue(kt + 1, (kt + 1) & 1); cp_wait<1>(); }
        else             { cp_wait<0>(); }
        __syncthreads();

#pragma unroll
        for (int ks = 0; ks < 4; ks++) {
            int kk = ks * 8;
            uint32_t a[4][4];
#pragma unroll
            for (int mf = 0; mf < 4; mf++) {
                int rb = wm + mf * 16;
                a[mf][0] = f2tfu(sA[buf][rb + (lane >> 2)][kk + (lane & 3)]);
                a[mf][1] = f2tfu(sA[buf][rb + 8 + (lane >> 2)][kk + (lane & 3)]);
                a[mf][2] = f2tfu(sA[buf][rb + (lane >> 2)][kk + 4 + (lane & 3)]);
                a[mf][3] = f2tfu(sA[buf][rb + 8 + (lane >> 2)][kk + 4 + (lane & 3)]);
            }
#pragma unroll
            for (int nf = 0; nf < 4; nf++) {
                int cb = wn + nf * 8 + (lane >> 2);
                uint32_t b0 = f2tfu(sB[buf][kk + (lane & 3)][cb]);
                uint32_t b1 = f2tfu(sB[buf][kk + 4 + (lane & 3)][cb]);
#pragma unroll
                for (int mf = 0; mf < 4; mf++)
                    mma_tf32(acc[mf][nf], a[mf][0], a[mf][1], a[mf][2], a[mf][3], b0, b1);
            }
        }
        __syncthreads();
    }

    // epilogue: out[tok, col] += weight * acc  (exactly 2 adds per element -> deterministic)
#pragma unroll
    for (int mf = 0; mf < 4; mf++) {
#pragma unroll
        for (int half = 0; half < 2; half++) {
            int rl = wm + mf * 16 + (lane >> 2) + half * 8;
            int r = row0 + rl;
            if (r < rend) {
                int tok = sTok[rl];
                float s = sW[rl];
                float* op = out + (size_t)tok * D_DIM;
#pragma unroll
                for (int nf = 0; nf < 4; nf++) {
                    int col = n0 + wn + nf * 8 + (lane & 3) * 2;
                    atomicAdd(op + col,     acc[mf][nf][half * 2] * s);
                    atomicAdd(op + col + 1, acc[mf][nf][half * 2 + 1] * s);
                }
            }
        }
    }
}

// ---------------- entry ----------------
extern "C" void kernel_launch(void* const* d_in, const int* in_sizes, int n_in,
                              void* d_out, int out_size) {
    const float* x  = (const float*)d_in[0];   // hidden_states [4,2048,1024]
    const float* gw = (const float*)d_in[1];   // gate_w [8,1024]
    const float* w1 = (const float*)d_in[2];   // [8,1024,3584]
    const float* w3 = (const float*)d_in[3];   // [8,1024,3584]
    const float* w2 = (const float*)d_in[4];   // [8,3584,1024]

    float* out = (float*)d_out;                         // [T*D] moe output
    float* logits = out + (size_t)T_TOK * D_DIM;        // [T*E] router logits

    static bool attr_set = false;
    if (!attr_set) {
        cudaFuncSetAttribute(k_gemm1, cudaFuncAttributeMaxDynamicSharedMemorySize, G1_SMEM);
        cudaFuncSetAttribute(k_gemm2, cudaFuncAttributeMaxDynamicSharedMemorySize, G2_SMEM);
        attr_set = true;
    }

    k_reset<<<1, 32>>>();
    k_router<<<T_TOK, 256>>>(x, gw, logits);
    k_scan<<<1, 1>>>();
    k_scatter<<<T_TOK / 256, 256>>>();
    k_zero<<<2048, 256>>>((float4*)out, (T_TOK * D_DIM) / 4);

    dim3 g1(MAX_TILES, F_DIM / 64);
    k_gemm1<<<g1, 256, G1_SMEM>>>(x, w1, w3);

    dim3 g2(MAX_TILES, D_DIM / 128);
    k_gemm2<<<g2, 256, G2_SMEM>>>(w2, out);
}

// round 7
// speedup vs baseline: 1.9072x; 1.0011x over previous
#include <cuda_runtime.h>
#include <cuda_bf16.h>
#include <cstdint>

#define T_TOK 8192
#define D_DIM 1024
#define F_DIM 3584
#define N_EXP 8
#define N_ASSIGN (T_TOK * 2)
#define BM 128
#define BK 32
#define MAX_TILES (N_ASSIGN / BM + N_EXP)  // 136
#define W_ELEMS ((size_t)N_EXP * D_DIM * F_DIM)   // 29,360,128 per tensor

// ---------------- scratch (static __device__, allocation-free) ----------------
__device__ float g_h  [(size_t)N_ASSIGN * F_DIM];  // SwiGLU out, tf32-rounded
__device__ float g_xr [(size_t)T_TOK * D_DIM];     // x,  tf32-rounded
__device__ float g_w1r[W_ELEMS];                   // w1, tf32-rounded [E][K][N]
__device__ float g_w3r[W_ELEMS];
__device__ float g_w2r[W_ELEMS];                   // [E][F][D]
__device__ int   g_rowtok[N_ASSIGN];
__device__ float g_roww[N_ASSIGN];
__device__ int   g_route_e[N_ASSIGN];
__device__ float g_route_w[N_ASSIGN];
__device__ int   g_cnt[N_EXP];
__device__ int   g_cur[N_EXP];
__device__ int   g_off[N_EXP + 1];
__device__ int   g_tile_e[MAX_TILES];
__device__ int   g_tile_r0[MAX_TILES];
__device__ int   g_tile_rend[MAX_TILES];
__device__ int   g_ntiles;

// ---------------- helpers ----------------
__device__ __forceinline__ float f2tf(float f) {
    // round-to-nearest tf32 (unbiased); HW mma truncates, so rounding must be explicit
    uint32_t r;
    asm("cvt.rna.tf32.f32 %0, %1;" : "=r"(r) : "f"(f));
    return __uint_as_float(r);
}

__device__ __forceinline__ void mma_tf32(float c[4], uint32_t a0, uint32_t a1,
                                         uint32_t a2, uint32_t a3,
                                         uint32_t b0, uint32_t b1) {
    asm volatile(
        "mma.sync.aligned.m16n8k8.row.col.f32.tf32.tf32.f32 "
        "{%0,%1,%2,%3}, {%4,%5,%6,%7}, {%8,%9}, {%0,%1,%2,%3};\n"
        : "+f"(c[0]), "+f"(c[1]), "+f"(c[2]), "+f"(c[3])
        : "r"(a0), "r"(a1), "r"(a2), "r"(a3), "r"(b0), "r"(b1));
}

__device__ __forceinline__ void cp16(void* s, const void* g) {
    uint32_t sa = (uint32_t)__cvta_generic_to_shared(s);
    asm volatile("cp.async.cg.shared.global [%0], [%1], 16;\n" :: "r"(sa), "l"(g));
}
__device__ __forceinline__ void cp16p(void* s, const void* g, bool p) {
    uint32_t sa = (uint32_t)__cvta_generic_to_shared(s);
    int b = p ? 16 : 0;
    asm volatile("cp.async.cg.shared.global [%0], [%1], 16, %2;\n" :: "r"(sa), "l"(g), "r"(b));
}
__device__ __forceinline__ void cp_commit() {
    asm volatile("cp.async.commit_group;\n" ::: "memory");
}
template <int N>
__device__ __forceinline__ void cp_wait() {
    asm volatile("cp.async.wait_group %0;\n" :: "n"(N) : "memory");
}

// ---------------- prepass: tf32-round tensors ----------------
__global__ void k_round(const float4* __restrict__ src, float4* __restrict__ dst, int n4) {
    int stride = gridDim.x * blockDim.x;
    for (int i = blockIdx.x * blockDim.x + threadIdx.x; i < n4; i += stride) {
        float4 v = src[i];
        dst[i] = make_float4(f2tf(v.x), f2tf(v.y), f2tf(v.z), f2tf(v.w));
    }
}

// ---------------- small kernels ----------------
__global__ void k_reset() {
    int i = threadIdx.x;
    if (i < N_EXP) { g_cnt[i] = 0; g_cur[i] = 0; }
}

__global__ void k_zero(float4* p, int n4) {
    int stride = gridDim.x * blockDim.x;
    for (int i = blockIdx.x * blockDim.x + threadIdx.x; i < n4; i += stride)
        p[i] = make_float4(0.f, 0.f, 0.f, 0.f);
}

__global__ void k_router(const float* __restrict__ x, const float* __restrict__ gw,
                         float* __restrict__ logits_out) {
    int t = blockIdx.x;
    int tid = threadIdx.x;                 // 256 threads
    const float* xr = x + (size_t)t * D_DIM;

    float acc[N_EXP];
#pragma unroll
    for (int e = 0; e < N_EXP; e++) acc[e] = 0.f;

    for (int j = tid; j < D_DIM; j += 256) {
        float xv = xr[j];
#pragma unroll
        for (int e = 0; e < N_EXP; e++) acc[e] += xv * gw[e * D_DIM + j];
    }
#pragma unroll
    for (int e = 0; e < N_EXP; e++)
#pragma unroll
        for (int o = 16; o > 0; o >>= 1)
            acc[e] += __shfl_xor_sync(0xffffffffu, acc[e], o);

    __shared__ float wsum[8][N_EXP];
    __shared__ float sl[N_EXP];
    int wid = tid >> 5, lane = tid & 31;
    if (lane == 0) {
#pragma unroll
        for (int e = 0; e < N_EXP; e++) wsum[wid][e] = acc[e];
    }
    __syncthreads();
    if (tid < N_EXP) {
        float s = 0.f;
#pragma unroll
        for (int w = 0; w < 8; w++) s += wsum[w][tid];
        sl[tid] = s;
        logits_out[(size_t)t * N_EXP + tid] = s;   // raw router logits output
    }
    __syncthreads();
    if (tid == 0) {
        float l[N_EXP];
#pragma unroll
        for (int e = 0; e < N_EXP; e++) l[e] = sl[e];
        int i0 = 0;
#pragma unroll
        for (int e = 1; e < N_EXP; e++) if (l[e] > l[i0]) i0 = e;
        int i1 = (i0 == 0) ? 1 : 0;
#pragma unroll
        for (int e = 0; e < N_EXP; e++) if (e != i0 && l[e] > l[i1]) i1 = e;
        float r = __expf(l[i1] - l[i0]);
        float w0 = 1.f / (1.f + r);
        float w1 = r / (1.f + r);
        g_route_e[2 * t] = i0;  g_route_w[2 * t] = w0;
        g_route_e[2 * t + 1] = i1; g_route_w[2 * t + 1] = w1;
        atomicAdd(&g_cnt[i0], 1);
        atomicAdd(&g_cnt[i1], 1);
    }
}

__global__ void k_scan() {
    if (blockIdx.x == 0 && threadIdx.x == 0) {
        int off = 0;
        for (int e = 0; e < N_EXP; e++) { g_off[e] = off; off += g_cnt[e]; g_cur[e] = 0; }
        g_off[N_EXP] = off;
        int nt = 0;
        for (int e = 0; e < N_EXP; e++) {
            int c = g_cnt[e], r0 = g_off[e];
            int m = (c + BM - 1) / BM;
            for (int i = 0; i < m; i++) {
                g_tile_e[nt] = e;
                g_tile_r0[nt] = r0 + i * BM;
                g_tile_rend[nt] = r0 + c;
                nt++;
            }
        }
        g_ntiles = nt;
    }
}

__global__ void k_scatter() {
    int t = blockIdx.x * blockDim.x + threadIdx.x;
    if (t < T_TOK) {
#pragma unroll
        for (int k = 0; k < 2; k++) {
            int e = g_route_e[2 * t + k];
            int p = g_off[e] + atomicAdd(&g_cur[e], 1);
            g_rowtok[p] = t;
            g_roww[p] = g_route_w[2 * t + k];
        }
    }
}

// ---------------- GEMM1: H = silu(Xg @ W1) * (Xg @ W3), fused, tf32 ----------------
// block tile: 128 x 64 (both w1 & w3) x K=1024; operands pre-rounded; no cvt in loop
#define G1_SMEM ((2 * 128 * 36 + 2 * 2 * 32 * 68) * 4)
__global__ __launch_bounds__(256, 2)
void k_gemm1() {
    int tile = blockIdx.x;
    if (tile >= g_ntiles) return;
    int e = g_tile_e[tile], row0 = g_tile_r0[tile], rend = g_tile_rend[tile];
    int n0 = blockIdx.y * 64;

    extern __shared__ float dyn[];
    float (*sA)[BM][36]     = (float (*)[BM][36])dyn;                 // [2][128][36]
    float (*sB)[2][BK][68]  = (float (*)[2][BK][68])(dyn + 2 * BM * 36);

    __shared__ int sTok[BM];

    int tid = threadIdx.x;
    if (tid < BM) {
        int r = row0 + tid;
        sTok[tid] = (r < rend) ? g_rowtok[r] : -1;
    }
    __syncthreads();

    const float* wb0 = g_w1r + (size_t)e * D_DIM * F_DIM;
    const float* wb1 = g_w3r + (size_t)e * D_DIM * F_DIM;

    int wid = tid >> 5, lane = tid & 31;
    int wm = (wid & 3) * 32, wn = (wid >> 2) * 32;

    int arow[4], ac4[4];
    const float* asrc[4];
    bool apred[4];
#pragma unroll
    for (int i = 0; i < 4; i++) {
        int idx = i * 256 + tid;
        arow[i] = idx >> 3; ac4[i] = idx & 7;
        int tok = sTok[arow[i]];
        asrc[i] = (tok >= 0) ? (g_xr + (size_t)tok * D_DIM + ac4[i] * 4) : g_xr;
        apred[i] = (tok >= 0);
    }

    auto issue = [&](int kt, int buf) {
#pragma unroll
        for (int i = 0; i < 4; i++)
            cp16p(&sA[buf][arow[i]][ac4[i] * 4], asrc[i] + kt * BK, apred[i]);
#pragma unroll
        for (int m = 0; m < 2; m++) {
            const float* wb = m ? wb1 : wb0;
#pragma unroll
            for (int i = 0; i < 2; i++) {
                int idx = i * 256 + tid;
                int kr = idx >> 4, c4 = idx & 15;
                cp16(&sB[buf][m][kr][c4 * 4],
                     wb + (size_t)(kt * BK + kr) * F_DIM + n0 + c4 * 4);
            }
        }
        cp_commit();
    };

    float accP[2][4][4], accQ[2][4][4];
#pragma unroll
    for (int i = 0; i < 2; i++)
#pragma unroll
        for (int j = 0; j < 4; j++)
#pragma unroll
            for (int k = 0; k < 4; k++) { accP[i][j][k] = 0.f; accQ[i][j][k] = 0.f; }

    const int NK = D_DIM / BK;             // 32
    issue(0, 0);

    for (int kt = 0; kt < NK; kt++) {
        int buf = kt & 1;
        if (kt + 1 < NK) { issue(kt + 1, (kt + 1) & 1); cp_wait<1>(); }
        else             { cp_wait<0>(); }
        __syncthreads();

#pragma unroll
        for (int ks = 0; ks < 4; ks++) {
            int kk = ks * 8;
            uint32_t a[2][4];
#pragma unroll
            for (int mf = 0; mf < 2; mf++) {
                int rb = wm + mf * 16;
                a[mf][0] = __float_as_uint(sA[buf][rb + (lane >> 2)][kk + (lane & 3)]);
                a[mf][1] = __float_as_uint(sA[buf][rb + 8 + (lane >> 2)][kk + (lane & 3)]);
                a[mf][2] = __float_as_uint(sA[buf][rb + (lane >> 2)][kk + 4 + (lane & 3)]);
                a[mf][3] = __float_as_uint(sA[buf][rb + 8 + (lane >> 2)][kk + 4 + (lane & 3)]);
            }
#pragma unroll
            for (int nf = 0; nf < 4; nf++) {
                int cb = wn + nf * 8 + (lane >> 2);
                uint32_t p0 = __float_as_uint(sB[buf][0][kk + (lane & 3)][cb]);
                uint32_t p1 = __float_as_uint(sB[buf][0][kk + 4 + (lane & 3)][cb]);
                uint32_t q0 = __float_as_uint(sB[buf][1][kk + (lane & 3)][cb]);
                uint32_t q1 = __float_as_uint(sB[buf][1][kk + 4 + (lane & 3)][cb]);
#pragma unroll
                for (int mf = 0; mf < 2; mf++) {
                    mma_tf32(accP[mf][nf], a[mf][0], a[mf][1], a[mf][2], a[mf][3], p0, p1);
                    mma_tf32(accQ[mf][nf], a[mf][0], a[mf][1], a[mf][2], a[mf][3], q0, q1);
                }
            }
        }
        __syncthreads();
    }

    // epilogue: h = silu(p) * q, stored tf32-rounded (so GEMM2 needs no cvt)
#pragma unroll
    for (int mf = 0; mf < 2; mf++) {
#pragma unroll
        for (int half = 0; half < 2; half++) {
            int rl = wm + mf * 16 + (lane >> 2) + half * 8;
            int r = row0 + rl;
            if (r < rend) {
#pragma unroll
                for (int nf = 0; nf < 4; nf++) {
                    int col = n0 + wn + nf * 8 + (lane & 3) * 2;
                    float p0 = accP[mf][nf][half * 2], p1 = accP[mf][nf][half * 2 + 1];
                    float q0 = accQ[mf][nf][half * 2], q1 = accQ[mf][nf][half * 2 + 1];
                    float h0 = f2tf((p0 / (1.f + __expf(-p0))) * q0);
                    float h1 = f2tf((p1 / (1.f + __expf(-p1))) * q1);
                    *(float2*)(g_h + (size_t)r * F_DIM + col) = make_float2(h0, h1);
                }
            }
        }
    }
}

// ---------------- GEMM2: Y = H @ W2[e], scaled scatter-add ----------------
#define G2_SMEM ((2 * 128 * 36 + 2 * 32 * 132) * 4)
__global__ __launch_bounds__(256, 2)
void k_gemm2(float* __restrict__ out) {
    int tile = blockIdx.x;
    if (tile >= g_ntiles) return;
    int e = g_tile_e[tile], row0 = g_tile_r0[tile], rend = g_tile_rend[tile];
    int n0 = blockIdx.y * 128;

    extern __shared__ float dyn[];
    float (*sA)[BM][36]  = (float (*)[BM][36])dyn;
    float (*sB)[BK][132] = (float (*)[BK][132])(dyn + 2 * BM * 36);

    __shared__ int   sTok[BM];
    __shared__ float sW[BM];

    int tid = threadIdx.x;
    if (tid < BM) {
        int r = row0 + tid;
        sTok[tid] = (r < rend) ? g_rowtok[r] : 0;
        sW[tid]   = (r < rend) ? g_roww[r] : 0.f;
    }
    __syncthreads();

    const float* wb = g_w2r + (size_t)e * F_DIM * D_DIM;
    int wid = tid >> 5, lane = tid & 31;
    int wm = (wid & 1) * 64, wn = (wid >> 1) * 32;

    int arow[4], ac4[4];
    bool apred[4];
#pragma unroll
    for (int i = 0; i < 4; i++) {
        int idx = i * 256 + tid;
        arow[i] = idx >> 3; ac4[i] = idx & 7;
        apred[i] = (row0 + arow[i]) < rend;
    }

    auto issue = [&](int kt, int buf) {
#pragma unroll
        for (int i = 0; i < 4; i++)
            cp16p(&sA[buf][arow[i]][ac4[i] * 4],
                  g_h + (size_t)(row0 + arow[i]) * F_DIM + kt * BK + ac4[i] * 4,
                  apred[i]);
#pragma unroll
        for (int i = 0; i < 4; i++) {
            int idx = i * 256 + tid;
            int kr = idx >> 5, c4 = idx & 31;
            cp16(&sB[buf][kr][c4 * 4],
                 wb + (size_t)(kt * BK + kr) * D_DIM + n0 + c4 * 4);
        }
        cp_commit();
    };

    float acc[4][4][4];
#pragma unroll
    for (int i = 0; i < 4; i++)
#pragma unroll
        for (int j = 0; j < 4; j++)
#pragma unroll
            for (int k = 0; k < 4; k++) acc[i][j][k] = 0.f;

    const int NK = F_DIM / BK;             // 112
    issue(0, 0);

    for (int kt = 0; kt < NK; kt++) {
        int buf = kt & 1;
        if (kt + 1 < NK) { issue(kt + 1, (kt + 1) & 1); cp_wait<1>(); }
        else             { cp_wait<0>(); }
        __syncthreads();

#pragma unroll
        for (int ks = 0; ks < 4; ks++) {
            int kk = ks * 8;
            uint32_t a[4][4];
#pragma unroll
            for (int mf = 0; mf < 4; mf++) {
                int rb = wm + mf * 16;
                a[mf][0] = __float_as_uint(sA[buf][rb + (lane >> 2)][kk + (lane & 3)]);
                a[mf][1] = __float_as_uint(sA[buf][rb + 8 + (lane >> 2)][kk + (lane & 3)]);
                a[mf][2] = __float_as_uint(sA[buf][rb + (lane >> 2)][kk + 4 + (lane & 3)]);
                a[mf][3] = __float_as_uint(sA[buf][rb + 8 + (lane >> 2)][kk + 4 + (lane & 3)]);
            }
#pragma unroll
            for (int nf = 0; nf < 4; nf++) {
                int cb = wn + nf * 8 + (lane >> 2);
                uint32_t b0 = __float_as_uint(sB[buf][kk + (lane & 3)][cb]);
                uint32_t b1 = __float_as_uint(sB[buf][kk + 4 + (lane & 3)][cb]);
#pragma unroll
                for (int mf = 0; mf < 4; mf++)
                    mma_tf32(acc[mf][nf], a[mf][0], a[mf][1], a[mf][2], a[mf][3], b0, b1);
            }
        }
        __syncthreads();
    }

#pragma unroll
    for (int mf = 0; mf < 4; mf++) {
#pragma unroll
        for (int half = 0; half < 2; half++) {
            int rl = wm + mf * 16 + (lane >> 2) + half * 8;
            int r = row0 + rl;
            if (r < rend) {
                int tok = sTok[rl];
                float s = sW[rl];
                float* op = out + (size_t)tok * D_DIM;
#pragma unroll
                for (int nf = 0; nf < 4; nf++) {
                    int col = n0 + wn + nf * 8 + (lane & 3) * 2;
                    atomicAdd(op + col,     acc[mf][nf][half * 2] * s);
                    atomicAdd(op + col + 1, acc[mf][nf][half * 2 + 1] * s);
                }
            }
        }
    }
}

// ---------------- entry ----------------
extern "C" void kernel_launch(void* const* d_in, const int* in_sizes, int n_in,
                              void* d_out, int out_size) {
    const float* x  = (const float*)d_in[0];   // hidden_states [4,2048,1024]
    const float* gw = (const float*)d_in[1];   // gate_w [8,1024]
    const float* w1 = (const float*)d_in[2];   // [8,1024,3584]
    const float* w3 = (const float*)d_in[3];   // [8,1024,3584]
    const float* w2 = (const float*)d_in[4];   // [8,3584,1024]

    float* out = (float*)d_out;                         // [T*D] moe output
    float* logits = out + (size_t)T_TOK * D_DIM;        // [T*E] router logits

    static bool attr_set = false;
    if (!attr_set) {
        cudaFuncSetAttribute(k_gemm1, cudaFuncAttributeMaxDynamicSharedMemorySize, G1_SMEM);
        cudaFuncSetAttribute(k_gemm2, cudaFuncAttributeMaxDynamicSharedMemorySize, G2_SMEM);
        attr_set = true;
    }

    float* xr  = nullptr; cudaGetSymbolAddress((void**)&xr,  g_xr);
    float* w1r = nullptr; cudaGetSymbolAddress((void**)&w1r, g_w1r);
    float* w3r = nullptr; cudaGetSymbolAddress((void**)&w3r, g_w3r);
    float* w2r = nullptr; cudaGetSymbolAddress((void**)&w2r, g_w2r);

    k_reset<<<1, 32>>>();
    // prepass: tf32-round all GEMM operands (bandwidth-bound, ~115us)
    k_round<<<2048, 256>>>((const float4*)x,  (float4*)xr,  (T_TOK * D_DIM) / 4);
    k_round<<<4096, 256>>>((const float4*)w1, (float4*)w1r, (int)(W_ELEMS / 4));
    k_round<<<4096, 256>>>((const float4*)w3, (float4*)w3r, (int)(W_ELEMS / 4));
    k_round<<<4096, 256>>>((const float4*)w2, (float4*)w2r, (int)(W_ELEMS / 4));

    k_router<<<T_TOK, 256>>>(x, gw, logits);
    k_scan<<<1, 1>>>();
    k_scatter<<<T_TOK / 256, 256>>>();
    k_zero<<<2048, 256>>>((float4*)out, (T_TOK * D_DIM) / 4);

    dim3 g1(MAX_TILES, F_DIM / 64);
    k_gemm1<<<g1, 256, G1_SMEM>>>();

    dim3 g2(MAX_TILES, D_DIM / 128);
    k_gemm2<<<g2, 256, G2_SMEM>>>(out);
}